// round 1
// baseline (speedup 1.0000x reference)
#include <cuda_runtime.h>
#include <cstdint>

#define HH 8
#define DD 512
#define BB 128
#define SS 2048
#define EE 4096   // HH*DD

// Scratch (no allocations allowed)
__device__ float g_q[BB * EE];   // projected, pre-scaled query  (B, H*D)
__device__ float g_x[BB * EE];   // attention output             (B, H*D)

__device__ __forceinline__ float dot4(float4 a, float4 b) {
    return a.x * b.x + a.y * b.y + a.z * b.z + a.w * b.w;
}
__device__ __forceinline__ void fma4(float4& a, float p, float4 v) {
    a.x += p * v.x; a.y += p * v.y; a.z += p * v.z; a.w += p * v.w;
}

// ---------------------------------------------------------------------------
// Kernel A: q = (query @ W_in^T + b_in) * (1/sqrt(D))
// One warp per output feature e; W row lives in registers, loop over batch.
// ---------------------------------------------------------------------------
__global__ void __launch_bounds__(256) qproj_kernel(const float* __restrict__ query,
                                                    const float* __restrict__ W_in,
                                                    const float* __restrict__ b_in) {
    const int warp = threadIdx.x >> 5;
    const int lane = threadIdx.x & 31;
    const int e = blockIdx.x * 8 + warp;

    const float4* Wr = (const float4*)(W_in + (size_t)e * DD);
    const float4 w0 = Wr[lane], w1 = Wr[lane + 32], w2 = Wr[lane + 64], w3 = Wr[lane + 96];
    const float bias = b_in[e];
    const float scale = 0.04419417382415922f;  // 1/sqrt(512)

    for (int b = 0; b < BB; b++) {
        const float4* qr = (const float4*)(query + (size_t)b * DD);
        float4 a0 = qr[lane], a1 = qr[lane + 32], a2 = qr[lane + 64], a3 = qr[lane + 96];
        float acc = dot4(a0, w0) + dot4(a1, w1) + dot4(a2, w2) + dot4(a3, w3);
        #pragma unroll
        for (int off = 16; off; off >>= 1)
            acc += __shfl_xor_sync(0xffffffffu, acc, off);
        if (lane == 0)
            g_q[(size_t)b * EE + e] = (acc + bias) * scale;
    }
}

// ---------------------------------------------------------------------------
// Kernel B: attention. One CTA per batch b.
//  smem: q_s[8*512] (pre-scaled q), sc[2048][8] (scores, s-major transposed)
//  pass1: warp-per-s, dot over D for all 8 heads, butterfly-reduce, mask
//  softmax: warp-per-head
//  pass2: thread owns (head-quad, d-float4), s split across 4 groups,
//         partials combined through smem (sc reused as scratch)
// ---------------------------------------------------------------------------
__global__ void __launch_bounds__(1024, 1) attn_kernel(const float* __restrict__ key,
                                                       const float* __restrict__ value,
                                                       const int* __restrict__ mask) {
    extern __shared__ float smem[];
    float* q_s = smem;            // 4096 floats
    float* sc  = smem + EE;       // 2048*8 = 16384 floats

    const int b = blockIdx.x;
    const int tid = threadIdx.x;
    const int warp = tid >> 5;
    const int lane = tid & 31;

    // load q (already scaled by 1/sqrt(D))
    ((float4*)q_s)[tid] = ((const float4*)(g_q + (size_t)b * EE))[tid];
    __syncthreads();

    // ---- pass 1: scores ----
    const float* Kb = key + (size_t)b * SS * DD;
    const int*   Mb = mask + (size_t)b * SS;

    #pragma unroll 2
    for (int s = warp; s < SS; s += 32) {
        const float4* Kr = (const float4*)(Kb + (size_t)s * DD);
        float4 k0 = Kr[lane], k1 = Kr[lane + 32], k2 = Kr[lane + 64], k3 = Kr[lane + 96];
        float acc[HH];
        #pragma unroll
        for (int h = 0; h < HH; h++) {
            const float4* qh = (const float4*)(q_s + h * DD);
            float4 a0 = qh[lane], a1 = qh[lane + 32], a2 = qh[lane + 64], a3 = qh[lane + 96];
            acc[h] = dot4(a0, k0) + dot4(a1, k1) + dot4(a2, k2) + dot4(a3, k3);
        }
        #pragma unroll
        for (int off = 16; off; off >>= 1) {
            #pragma unroll
            for (int h = 0; h < HH; h++)
                acc[h] += __shfl_xor_sync(0xffffffffu, acc[h], off);
        }
        const int mv = Mb[s];
        #pragma unroll
        for (int h = 0; h < HH; h++)
            if (lane == h) sc[s * 8 + h] = mv ? acc[h] : -1e9f;
    }
    __syncthreads();

    // ---- softmax: warp h handles head h ----
    if (warp < HH) {
        float m = -3.0e38f;
        for (int i = lane; i < SS; i += 32) m = fmaxf(m, sc[i * 8 + warp]);
        #pragma unroll
        for (int off = 16; off; off >>= 1)
            m = fmaxf(m, __shfl_xor_sync(0xffffffffu, m, off));
        float sum = 0.0f;
        for (int i = lane; i < SS; i += 32) {
            float ev = __expf(sc[i * 8 + warp] - m);
            sc[i * 8 + warp] = ev;
            sum += ev;
        }
        #pragma unroll
        for (int off = 16; off; off >>= 1)
            sum += __shfl_xor_sync(0xffffffffu, sum, off);
        const float inv = 1.0f / sum;
        for (int i = lane; i < SS; i += 32) sc[i * 8 + warp] *= inv;
    }
    __syncthreads();

    // ---- pass 2: x = p @ V ----
    const int d4 = (tid & 127) * 4;          // which 4 d's this thread owns
    const int h0 = ((tid >> 7) & 1) * 4;     // head quad: 0..3 or 4..7
    const int sg = tid >> 8;                 // s quarter: 0..3
    const float* Vb = value + (size_t)b * SS * DD;

    float4 acc0 = {0, 0, 0, 0}, acc1 = acc0, acc2 = acc0, acc3 = acc0;
    const int s_beg = sg * 512;
    #pragma unroll 2
    for (int s = s_beg; s < s_beg + 512; s += 2) {
        float4 v0 = *(const float4*)(Vb + (size_t)s * DD + d4);
        float4 v1 = *(const float4*)(Vb + (size_t)(s + 1) * DD + d4);
        float4 p0 = *(const float4*)(sc + s * 8 + h0);
        float4 p1 = *(const float4*)(sc + (s + 1) * 8 + h0);
        fma4(acc0, p0.x, v0); fma4(acc1, p0.y, v0); fma4(acc2, p0.z, v0); fma4(acc3, p0.w, v0);
        fma4(acc0, p1.x, v1); fma4(acc1, p1.y, v1); fma4(acc2, p1.z, v1); fma4(acc3, p1.w, v1);
    }
    __syncthreads();  // everyone done reading sc

    // store partials into sc (reused as scratch): [sg][h][d]
    *(float4*)(sc + sg * 4096 + (h0 + 0) * DD + d4) = acc0;
    *(float4*)(sc + sg * 4096 + (h0 + 1) * DD + d4) = acc1;
    *(float4*)(sc + sg * 4096 + (h0 + 2) * DD + d4) = acc2;
    *(float4*)(sc + sg * 4096 + (h0 + 3) * DD + d4) = acc3;
    __syncthreads();

    // final combine across 4 s-groups; write x
    const int idx = tid * 4;
    float4 r0 = *(float4*)(sc + 0 * 4096 + idx);
    float4 r1 = *(float4*)(sc + 1 * 4096 + idx);
    float4 r2 = *(float4*)(sc + 2 * 4096 + idx);
    float4 r3 = *(float4*)(sc + 3 * 4096 + idx);
    float4 r;
    r.x = r0.x + r1.x + r2.x + r3.x;
    r.y = r0.y + r1.y + r2.y + r3.y;
    r.z = r0.z + r1.z + r2.z + r3.z;
    r.w = r0.w + r1.w + r2.w + r3.w;
    *(float4*)(g_x + (size_t)b * EE + idx) = r;
}

// ---------------------------------------------------------------------------
// Kernel C: out = x @ W_out^T + b_out      (128 x 4096) @ (4096 x 4096)^T
// SGEMM: BM=128 (all b), BN=32, BK=32, 256 threads, reg-prefetch pipeline.
// ---------------------------------------------------------------------------
__global__ void __launch_bounds__(256) outproj_kernel(const float* __restrict__ W_out,
                                                      const float* __restrict__ b_out,
                                                      float* __restrict__ out) {
    __shared__ float xs[32][132];   // [k][b]  (+4 pad)
    __shared__ float ws[32][36];    // [k][f]  (+4 pad)

    const int tid = threadIdx.x;
    const int fbase = blockIdx.x * 32;
    const int tx = tid & 15;        // f pair index
    const int ty = tid >> 4;        // b octet index

    const int lrow = tid >> 3;      // 0..31
    const int lk   = (tid & 7) * 4; // 0..28

    const float* Wb = W_out + (size_t)(fbase + lrow) * EE;

    float acc[8][2] = {};
    float4 px[4], pw;

    // prefetch tile 0
    #pragma unroll
    for (int r = 0; r < 4; r++)
        px[r] = *(const float4*)(g_x + (size_t)(lrow + r * 32) * EE + lk);
    pw = *(const float4*)(Wb + lk);

    #pragma unroll
    for (int r = 0; r < 4; r++) {
        xs[lk + 0][lrow + r * 32] = px[r].x;
        xs[lk + 1][lrow + r * 32] = px[r].y;
        xs[lk + 2][lrow + r * 32] = px[r].z;
        xs[lk + 3][lrow + r * 32] = px[r].w;
    }
    ws[lk + 0][lrow] = pw.x;
    ws[lk + 1][lrow] = pw.y;
    ws[lk + 2][lrow] = pw.z;
    ws[lk + 3][lrow] = pw.w;
    __syncthreads();

    const int NT = EE / 32;  // 128 k-tiles
    for (int t = 0; t < NT; t++) {
        if (t + 1 < NT) {
            const int k0 = (t + 1) * 32;
            #pragma unroll
            for (int r = 0; r < 4; r++)
                px[r] = *(const float4*)(g_x + (size_t)(lrow + r * 32) * EE + k0 + lk);
            pw = *(const float4*)(Wb + k0 + lk);
        }
        #pragma unroll 8
        for (int k = 0; k < 32; k++) {
            float4 a0 = *(const float4*)&xs[k][ty * 8];
            float4 a1 = *(const float4*)&xs[k][ty * 8 + 4];
            float2 bv = *(const float2*)&ws[k][tx * 2];
            float av[8] = {a0.x, a0.y, a0.z, a0.w, a1.x, a1.y, a1.z, a1.w};
            #pragma unroll
            for (int i = 0; i < 8; i++) {
                acc[i][0] += av[i] * bv.x;
                acc[i][1] += av[i] * bv.y;
            }
        }
        __syncthreads();
        if (t + 1 < NT) {
            #pragma unroll
            for (int r = 0; r < 4; r++) {
                xs[lk + 0][lrow + r * 32] = px[r].x;
                xs[lk + 1][lrow + r * 32] = px[r].y;
                xs[lk + 2][lrow + r * 32] = px[r].z;
                xs[lk + 3][lrow + r * 32] = px[r].w;
            }
            ws[lk + 0][lrow] = pw.x;
            ws[lk + 1][lrow] = pw.y;
            ws[lk + 2][lrow] = pw.z;
            ws[lk + 3][lrow] = pw.w;
            __syncthreads();
        }
    }

    const float b0 = b_out[fbase + tx * 2];
    const float b1 = b_out[fbase + tx * 2 + 1];
    #pragma unroll
    for (int i = 0; i < 8; i++) {
        float2 o;
        o.x = acc[i][0] + b0;
        o.y = acc[i][1] + b1;
        *(float2*)&out[(size_t)(ty * 8 + i) * EE + fbase + tx * 2] = o;
    }
}

// ---------------------------------------------------------------------------
extern "C" void kernel_launch(void* const* d_in, const int* in_sizes, int n_in,
                              void* d_out, int out_size) {
    const float* query = (const float*)d_in[0];
    const float* key   = (const float*)d_in[1];
    const float* value = (const float*)d_in[2];
    const int*   mask  = (const int*)d_in[3];
    const float* W_in  = (const float*)d_in[4];
    const float* b_in  = (const float*)d_in[5];
    const float* W_out = (const float*)d_in[6];
    const float* b_out = (const float*)d_in[7];
    float* out = (float*)d_out;

    const int smem_attn = (EE + SS * 8) * sizeof(float);  // 81920 bytes
    cudaFuncSetAttribute(attn_kernel, cudaFuncAttributeMaxDynamicSharedMemorySize, smem_attn);

    qproj_kernel<<<EE / 8, 256>>>(query, W_in, b_in);
    attn_kernel<<<BB, 1024, smem_attn>>>(key, value, mask);
    outproj_kernel<<<EE / 32, 256>>>(W_out, b_out, out);
}

// round 4
// speedup vs baseline: 1.4343x; 1.4343x over previous
#include <cuda_runtime.h>
#include <cuda_bf16.h>
#include <cstdint>

#define HH 8
#define DD 512
#define BB 128
#define SS 2048
#define EE 4096   // HH*DD
#define KSPLIT 4

// Scratch (no allocations allowed)
__device__ float g_q[BB * EE];            // projected, pre-scaled query
__device__ float g_x[BB * EE];            // attention output
__device__ float g_part[KSPLIT * BB * EE];// k-split GEMM partials

// Single dynamic-smem symbol for the whole TU
extern __shared__ char dyn_smem[];

__device__ __forceinline__ float dot4(float4 a, float4 b) {
    return a.x * b.x + a.y * b.y + a.z * b.z + a.w * b.w;
}
__device__ __forceinline__ void fma4(float4& a, float p, float4 v) {
    a.x += p * v.x; a.y += p * v.y; a.z += p * v.z; a.w += p * v.w;
}

// m16n8k16 row.col bf16 mma, fp32 accumulate (standard PTX, sm_80+)
__device__ __forceinline__ void mma16816(float* c, const uint32_t* a, const uint32_t* b) {
    asm volatile(
        "mma.sync.aligned.m16n8k16.row.col.f32.bf16.bf16.f32 "
        "{%0,%1,%2,%3}, {%4,%5,%6,%7}, {%8,%9}, {%0,%1,%2,%3};"
        : "+f"(c[0]), "+f"(c[1]), "+f"(c[2]), "+f"(c[3])
        : "r"(a[0]), "r"(a[1]), "r"(a[2]), "r"(a[3]), "r"(b[0]), "r"(b[1]));
}

// ===========================================================================
// gemm_part<K, KCHUNK>: part[p] = X[128,K_range] @ W[4096,K_range]^T
// BM=128, BN=128 per CTA (grid.x = 32 f-tiles), p = blockIdx.y (k-split).
// bf16 hi/lo 3-term split, fp32 acc. Double-buffered smem, KSTEP=32.
// smem row stride = 20 words (16 data + 4 pad) -> conflict-free frag loads.
// ===========================================================================
#define KSTEP 32
#define SW 20                    // words per row in smem
#define ARR (128 * SW)           // words per array
#define GEMM_SMEM (2 * 4 * ARR * 4)  // 81920 bytes

template <int K, int KCHUNK>
__global__ void __launch_bounds__(256, 1)
gemm_part(const float* __restrict__ X, const float* __restrict__ W,
          float* __restrict__ part) {
    uint32_t* sw = (uint32_t*)dyn_smem;
    const int tid = threadIdx.x;
    const int wid = tid >> 5;
    const int lane = tid & 31;
    const int g = lane >> 2;          // 0..7
    const int tg = lane & 3;          // 0..3
    const int wm = wid >> 2;          // 0..1: M half (64 rows)
    const int wn = wid & 3;           // 0..3: N quarter (32 cols)
    const int fbase = blockIdx.x * 128;
    const int p = blockIdx.y;
    const int kbeg = p * KCHUNK;

    const int lrow = tid >> 3;        // 0..31? no: 256/8 = 32.. need 128 rows x 8 q4
    // loader mapping: idx = tid + i*256; row = idx>>3 (0..127), q4 = idx&7
    float acc[4][4][4];
    #pragma unroll
    for (int mi = 0; mi < 4; mi++)
        #pragma unroll
        for (int ni = 0; ni < 4; ni++)
            #pragma unroll
            for (int r = 0; r < 4; r++) acc[mi][ni][r] = 0.0f;

    const int NC = KCHUNK / KSTEP;

    for (int c = 0; c < NC; c++) {
        const int q = c & 1;
        uint32_t* Ah = sw + q * 4 * ARR;
        uint32_t* Al = Ah + ARR;
        uint32_t* Bh = Al + ARR;
        uint32_t* Bl = Bh + ARR;
        const int k0 = kbeg + c * KSTEP;

        // ---- load + convert chunk c into buffer q ----
        #pragma unroll
        for (int i = 0; i < 4; i++) {
            const int idx = tid + i * 256;
            const int row = idx >> 3, q4 = idx & 7;
            float4 v = *(const float4*)(X + (size_t)row * K + k0 + q4 * 4);
            __nv_bfloat162 h01 = __floats2bfloat162_rn(v.x, v.y);
            __nv_bfloat162 h23 = __floats2bfloat162_rn(v.z, v.w);
            float2 f01 = __bfloat1622float2(h01);
            float2 f23 = __bfloat1622float2(h23);
            __nv_bfloat162 l01 = __floats2bfloat162_rn(v.x - f01.x, v.y - f01.y);
            __nv_bfloat162 l23 = __floats2bfloat162_rn(v.z - f23.x, v.w - f23.y);
            const int off = row * SW + q4 * 2;
            *(uint2*)(Ah + off) = make_uint2(*(uint32_t*)&h01, *(uint32_t*)&h23);
            *(uint2*)(Al + off) = make_uint2(*(uint32_t*)&l01, *(uint32_t*)&l23);
        }
        #pragma unroll
        for (int i = 0; i < 4; i++) {
            const int idx = tid + i * 256;
            const int row = idx >> 3, q4 = idx & 7;
            float4 v = *(const float4*)(W + (size_t)(fbase + row) * K + k0 + q4 * 4);
            __nv_bfloat162 h01 = __floats2bfloat162_rn(v.x, v.y);
            __nv_bfloat162 h23 = __floats2bfloat162_rn(v.z, v.w);
            float2 f01 = __bfloat1622float2(h01);
            float2 f23 = __bfloat1622float2(h23);
            __nv_bfloat162 l01 = __floats2bfloat162_rn(v.x - f01.x, v.y - f01.y);
            __nv_bfloat162 l23 = __floats2bfloat162_rn(v.z - f23.x, v.w - f23.y);
            const int off = row * SW + q4 * 2;
            *(uint2*)(Bh + off) = make_uint2(*(uint32_t*)&h01, *(uint32_t*)&h23);
            *(uint2*)(Bl + off) = make_uint2(*(uint32_t*)&l01, *(uint32_t*)&l23);
        }
        __syncthreads();

        // ---- compute on buffer q: 2 k16 sub-steps ----
        #pragma unroll
        for (int sub = 0; sub < 2; sub++) {
            const int wb = sub * 8 + tg;
            uint32_t bh[4][2], bl[4][2];
            #pragma unroll
            for (int ni = 0; ni < 4; ni++) {
                const int r = wn * 32 + ni * 8 + g;
                bh[ni][0] = Bh[r * SW + wb];
                bh[ni][1] = Bh[r * SW + wb + 4];
                bl[ni][0] = Bl[r * SW + wb];
                bl[ni][1] = Bl[r * SW + wb + 4];
            }
            #pragma unroll
            for (int mi = 0; mi < 4; mi++) {
                const int r0 = wm * 64 + mi * 16 + g;
                const int r1 = r0 + 8;
                uint32_t ah[4], al[4];
                ah[0] = Ah[r0 * SW + wb];
                ah[1] = Ah[r1 * SW + wb];
                ah[2] = Ah[r0 * SW + wb + 4];
                ah[3] = Ah[r1 * SW + wb + 4];
                al[0] = Al[r0 * SW + wb];
                al[1] = Al[r1 * SW + wb];
                al[2] = Al[r0 * SW + wb + 4];
                al[3] = Al[r1 * SW + wb + 4];
                #pragma unroll
                for (int ni = 0; ni < 4; ni++) {
                    mma16816(acc[mi][ni], ah, bh[ni]);
                    mma16816(acc[mi][ni], al, bh[ni]);
                    mma16816(acc[mi][ni], ah, bl[ni]);
                }
            }
        }
        __syncthreads();
    }

    // ---- write partials ----
    float* pp = part + (size_t)p * BB * EE;
    #pragma unroll
    for (int mi = 0; mi < 4; mi++) {
        const int m0 = wm * 64 + mi * 16 + g;
        #pragma unroll
        for (int ni = 0; ni < 4; ni++) {
            const int col = fbase + wn * 32 + ni * 8 + tg * 2;
            *(float2*)(pp + (size_t)m0 * EE + col)       = make_float2(acc[mi][ni][0], acc[mi][ni][1]);
            *(float2*)(pp + (size_t)(m0 + 8) * EE + col) = make_float2(acc[mi][ni][2], acc[mi][ni][3]);
        }
    }
}

// out = (sum_p part[p] + bias) * scale
__global__ void __launch_bounds__(256) reduce_part(const float* __restrict__ bias,
                                                   float* __restrict__ out, float scale) {
    const int t = blockIdx.x * 256 + threadIdx.x;
    const int base = t * 4;
    const int col = base & (EE - 1);
    float4 a = *(const float4*)(g_part + base);
    float4 b = *(const float4*)(g_part + 1 * BB * EE + base);
    float4 c = *(const float4*)(g_part + 2 * BB * EE + base);
    float4 d = *(const float4*)(g_part + 3 * BB * EE + base);
    float4 bi = *(const float4*)(bias + col);
    float4 o;
    o.x = (a.x + b.x + c.x + d.x + bi.x) * scale;
    o.y = (a.y + b.y + c.y + d.y + bi.y) * scale;
    o.z = (a.z + b.z + c.z + d.z + bi.z) * scale;
    o.w = (a.w + b.w + c.w + d.w + bi.w) * scale;
    *(float4*)(out + base) = o;
}

// ---------------------------------------------------------------------------
// Kernel B: attention. One CTA per batch b.
// ---------------------------------------------------------------------------
__global__ void __launch_bounds__(1024, 1) attn_kernel(const float* __restrict__ key,
                                                       const float* __restrict__ value,
                                                       const int* __restrict__ mask) {
    float* smem = (float*)dyn_smem;
    float* q_s = smem;            // 4096 floats
    float* sc  = smem + EE;       // 2048*8 = 16384 floats

    const int b = blockIdx.x;
    const int tid = threadIdx.x;
    const int warp = tid >> 5;
    const int lane = tid & 31;

    ((float4*)q_s)[tid] = ((const float4*)(g_q + (size_t)b * EE))[tid];
    __syncthreads();

    // ---- pass 1: scores ----
    const float* Kb = key + (size_t)b * SS * DD;
    const int*   Mb = mask + (size_t)b * SS;

    #pragma unroll 2
    for (int s = warp; s < SS; s += 32) {
        const float4* Kr = (const float4*)(Kb + (size_t)s * DD);
        float4 k0 = Kr[lane], k1 = Kr[lane + 32], k2 = Kr[lane + 64], k3 = Kr[lane + 96];
        float acc[HH];
        #pragma unroll
        for (int h = 0; h < HH; h++) {
            const float4* qh = (const float4*)(q_s + h * DD);
            float4 a0 = qh[lane], a1 = qh[lane + 32], a2 = qh[lane + 64], a3 = qh[lane + 96];
            acc[h] = dot4(a0, k0) + dot4(a1, k1) + dot4(a2, k2) + dot4(a3, k3);
        }
        #pragma unroll
        for (int off = 16; off; off >>= 1) {
            #pragma unroll
            for (int h = 0; h < HH; h++)
                acc[h] += __shfl_xor_sync(0xffffffffu, acc[h], off);
        }
        const int mv = Mb[s];
        #pragma unroll
        for (int h = 0; h < HH; h++)
            if (lane == h) sc[s * 8 + h] = mv ? acc[h] : -1e9f;
    }
    __syncthreads();

    // ---- softmax: warp h handles head h ----
    if (warp < HH) {
        float m = -3.0e38f;
        for (int i = lane; i < SS; i += 32) m = fmaxf(m, sc[i * 8 + warp]);
        #pragma unroll
        for (int off = 16; off; off >>= 1)
            m = fmaxf(m, __shfl_xor_sync(0xffffffffu, m, off));
        float sum = 0.0f;
        for (int i = lane; i < SS; i += 32) {
            float ev = __expf(sc[i * 8 + warp] - m);
            sc[i * 8 + warp] = ev;
            sum += ev;
        }
        #pragma unroll
        for (int off = 16; off; off >>= 1)
            sum += __shfl_xor_sync(0xffffffffu, sum, off);
        const float inv = 1.0f / sum;
        for (int i = lane; i < SS; i += 32) sc[i * 8 + warp] *= inv;
    }
    __syncthreads();

    // ---- pass 2: x = p @ V.  Thread owns 4 d's, ALL 8 heads; s split 8 ways.
    const int d4 = (tid & 127) * 4;
    const int sg = tid >> 7;             // 0..7
    const float* Vb = value + (size_t)b * SS * DD;

    float4 a0 = {0,0,0,0}, a1 = a0, a2 = a0, a3 = a0, a4 = a0, a5 = a0, a6 = a0, a7 = a0;
    const int s_beg = sg * 256;
    #pragma unroll 2
    for (int s = s_beg; s < s_beg + 256; s++) {
        float4 v  = *(const float4*)(Vb + (size_t)s * DD + d4);
        float4 p0 = *(const float4*)(sc + s * 8);
        float4 p1 = *(const float4*)(sc + s * 8 + 4);
        fma4(a0, p0.x, v); fma4(a1, p0.y, v); fma4(a2, p0.z, v); fma4(a3, p0.w, v);
        fma4(a4, p1.x, v); fma4(a5, p1.y, v); fma4(a6, p1.z, v); fma4(a7, p1.w, v);
    }
    __syncthreads();

    if (sg < 4) {
        float* dst = sc + sg * 4096;
        *(float4*)(dst + 0 * DD + d4) = a0;
        *(float4*)(dst + 1 * DD + d4) = a1;
        *(float4*)(dst + 2 * DD + d4) = a2;
        *(float4*)(dst + 3 * DD + d4) = a3;
        *(float4*)(dst + 4 * DD + d4) = a4;
        *(float4*)(dst + 5 * DD + d4) = a5;
        *(float4*)(dst + 6 * DD + d4) = a6;
        *(float4*)(dst + 7 * DD + d4) = a7;
    }
    __syncthreads();
    if (sg >= 4) {
        float* dst = sc + (sg - 4) * 4096;
        float4* p;
        p = (float4*)(dst + 0 * DD + d4); p->x += a0.x; p->y += a0.y; p->z += a0.z; p->w += a0.w;
        p = (float4*)(dst + 1 * DD + d4); p->x += a1.x; p->y += a1.y; p->z += a1.z; p->w += a1.w;
        p = (float4*)(dst + 2 * DD + d4); p->x += a2.x; p->y += a2.y; p->z += a2.z; p->w += a2.w;
        p = (float4*)(dst + 3 * DD + d4); p->x += a3.x; p->y += a3.y; p->z += a3.z; p->w += a3.w;
        p = (float4*)(dst + 4 * DD + d4); p->x += a4.x; p->y += a4.y; p->z += a4.z; p->w += a4.w;
        p = (float4*)(dst + 5 * DD + d4); p->x += a5.x; p->y += a5.y; p->z += a5.z; p->w += a5.w;
        p = (float4*)(dst + 6 * DD + d4); p->x += a6.x; p->y += a6.y; p->z += a6.z; p->w += a6.w;
        p = (float4*)(dst + 7 * DD + d4); p->x += a7.x; p->y += a7.y; p->z += a7.z; p->w += a7.w;
    }
    __syncthreads();

    const int idx = tid * 4;
    float4 r0 = *(float4*)(sc + 0 * 4096 + idx);
    float4 r1 = *(float4*)(sc + 1 * 4096 + idx);
    float4 r2 = *(float4*)(sc + 2 * 4096 + idx);
    float4 r3 = *(float4*)(sc + 3 * 4096 + idx);
    float4 r;
    r.x = r0.x + r1.x + r2.x + r3.x;
    r.y = r0.y + r1.y + r2.y + r3.y;
    r.z = r0.z + r1.z + r2.z + r3.z;
    r.w = r0.w + r1.w + r2.w + r3.w;
    *(float4*)(g_x + (size_t)b * EE + idx) = r;
}

// ---------------------------------------------------------------------------
extern "C" void kernel_launch(void* const* d_in, const int* in_sizes, int n_in,
                              void* d_out, int out_size) {
    const float* query = (const float*)d_in[0];
    const float* key   = (const float*)d_in[1];
    const float* value = (const float*)d_in[2];
    const int*   mask  = (const int*)d_in[3];
    const float* W_in  = (const float*)d_in[4];
    const float* b_in  = (const float*)d_in[5];
    const float* W_out = (const float*)d_in[6];
    const float* b_out = (const float*)d_in[7];
    float* out = (float*)d_out;

    const int smem_attn = (EE + SS * 8) * sizeof(float);  // 81920 bytes
    cudaFuncSetAttribute(attn_kernel, cudaFuncAttributeMaxDynamicSharedMemorySize, smem_attn);
    cudaFuncSetAttribute(gemm_part<512, 128>,   cudaFuncAttributeMaxDynamicSharedMemorySize, GEMM_SMEM);
    cudaFuncSetAttribute(gemm_part<4096, 1024>, cudaFuncAttributeMaxDynamicSharedMemorySize, GEMM_SMEM);

    float* gq; cudaGetSymbolAddress((void**)&gq, g_q);
    float* gx; cudaGetSymbolAddress((void**)&gx, g_x);
    float* gp; cudaGetSymbolAddress((void**)&gp, g_part);

    dim3 ggrid(EE / 128, KSPLIT);

    gemm_part<512, 128><<<ggrid, 256, GEMM_SMEM>>>(query, W_in, gp);
    reduce_part<<<BB * EE / 1024, 256>>>(b_in, gq, 0.04419417382415922f);
    attn_kernel<<<BB, 1024, smem_attn>>>(key, value, mask);
    gemm_part<4096, 1024><<<ggrid, 256, GEMM_SMEM>>>(gx, W_out, gp);
    reduce_part<<<BB * EE / 1024, 256>>>(b_out, out, 1.0f);
}

// round 5
// speedup vs baseline: 1.6885x; 1.1772x over previous
#include <cuda_runtime.h>
#include <cuda_bf16.h>
#include <cstdint>

#define HH 8
#define DD 512
#define BB 128
#define SS 2048
#define EE 4096   // HH*DD
#define KSPLIT 4

// Scratch (no allocations allowed)
__device__ float g_q[BB * EE];            // projected, pre-scaled query
__device__ float g_x[BB * EE];            // attention output
__device__ float g_part[KSPLIT * BB * EE];// k-split GEMM partials

// Single dynamic-smem symbol for the whole TU
extern __shared__ char dyn_smem[];

__device__ __forceinline__ float dot4(float4 a, float4 b) {
    return a.x * b.x + a.y * b.y + a.z * b.z + a.w * b.w;
}
__device__ __forceinline__ void fma4(float4& a, float p, float4 v) {
    a.x += p * v.x; a.y += p * v.y; a.z += p * v.z; a.w += p * v.w;
}

// m16n8k16 row.col bf16 mma, fp32 accumulate (standard PTX, sm_80+)
__device__ __forceinline__ void mma16816(float* c, const uint32_t* a, const uint32_t* b) {
    asm volatile(
        "mma.sync.aligned.m16n8k16.row.col.f32.bf16.bf16.f32 "
        "{%0,%1,%2,%3}, {%4,%5,%6,%7}, {%8,%9}, {%0,%1,%2,%3};"
        : "+f"(c[0]), "+f"(c[1]), "+f"(c[2]), "+f"(c[3])
        : "r"(a[0]), "r"(a[1]), "r"(a[2]), "r"(a[3]), "r"(b[0]), "r"(b[1]));
}

// ===========================================================================
// gemm_part<K, KCHUNK>: part[p] = X[128,K_range] @ W[4096,K_range]^T
// ===========================================================================
#define KSTEP 32
#define SW 20                    // words per row in smem
#define ARR (128 * SW)           // words per array
#define GEMM_SMEM (2 * 4 * ARR * 4)  // 81920 bytes

template <int K, int KCHUNK>
__global__ void __launch_bounds__(256, 1)
gemm_part(const float* __restrict__ X, const float* __restrict__ W,
          float* __restrict__ part) {
    uint32_t* sw = (uint32_t*)dyn_smem;
    const int tid = threadIdx.x;
    const int wid = tid >> 5;
    const int lane = tid & 31;
    const int g = lane >> 2;          // 0..7
    const int tg = lane & 3;          // 0..3
    const int wm = wid >> 2;          // 0..1: M half (64 rows)
    const int wn = wid & 3;           // 0..3: N quarter (32 cols)
    const int fbase = blockIdx.x * 128;
    const int p = blockIdx.y;
    const int kbeg = p * KCHUNK;

    float acc[4][4][4];
    #pragma unroll
    for (int mi = 0; mi < 4; mi++)
        #pragma unroll
        for (int ni = 0; ni < 4; ni++)
            #pragma unroll
            for (int r = 0; r < 4; r++) acc[mi][ni][r] = 0.0f;

    const int NC = KCHUNK / KSTEP;

    for (int c = 0; c < NC; c++) {
        const int q = c & 1;
        uint32_t* Ah = sw + q * 4 * ARR;
        uint32_t* Al = Ah + ARR;
        uint32_t* Bh = Al + ARR;
        uint32_t* Bl = Bh + ARR;
        const int k0 = kbeg + c * KSTEP;

        #pragma unroll
        for (int i = 0; i < 4; i++) {
            const int idx = tid + i * 256;
            const int row = idx >> 3, q4 = idx & 7;
            float4 v = *(const float4*)(X + (size_t)row * K + k0 + q4 * 4);
            __nv_bfloat162 h01 = __floats2bfloat162_rn(v.x, v.y);
            __nv_bfloat162 h23 = __floats2bfloat162_rn(v.z, v.w);
            float2 f01 = __bfloat1622float2(h01);
            float2 f23 = __bfloat1622float2(h23);
            __nv_bfloat162 l01 = __floats2bfloat162_rn(v.x - f01.x, v.y - f01.y);
            __nv_bfloat162 l23 = __floats2bfloat162_rn(v.z - f23.x, v.w - f23.y);
            const int off = row * SW + q4 * 2;
            *(uint2*)(Ah + off) = make_uint2(*(uint32_t*)&h01, *(uint32_t*)&h23);
            *(uint2*)(Al + off) = make_uint2(*(uint32_t*)&l01, *(uint32_t*)&l23);
        }
        #pragma unroll
        for (int i = 0; i < 4; i++) {
            const int idx = tid + i * 256;
            const int row = idx >> 3, q4 = idx & 7;
            float4 v = *(const float4*)(W + (size_t)(fbase + row) * K + k0 + q4 * 4);
            __nv_bfloat162 h01 = __floats2bfloat162_rn(v.x, v.y);
            __nv_bfloat162 h23 = __floats2bfloat162_rn(v.z, v.w);
            float2 f01 = __bfloat1622float2(h01);
            float2 f23 = __bfloat1622float2(h23);
            __nv_bfloat162 l01 = __floats2bfloat162_rn(v.x - f01.x, v.y - f01.y);
            __nv_bfloat162 l23 = __floats2bfloat162_rn(v.z - f23.x, v.w - f23.y);
            const int off = row * SW + q4 * 2;
            *(uint2*)(Bh + off) = make_uint2(*(uint32_t*)&h01, *(uint32_t*)&h23);
            *(uint2*)(Bl + off) = make_uint2(*(uint32_t*)&l01, *(uint32_t*)&l23);
        }
        __syncthreads();

        #pragma unroll
        for (int sub = 0; sub < 2; sub++) {
            const int wb = sub * 8 + tg;
            uint32_t bh[4][2], bl[4][2];
            #pragma unroll
            for (int ni = 0; ni < 4; ni++) {
                const int r = wn * 32 + ni * 8 + g;
                bh[ni][0] = Bh[r * SW + wb];
                bh[ni][1] = Bh[r * SW + wb + 4];
                bl[ni][0] = Bl[r * SW + wb];
                bl[ni][1] = Bl[r * SW + wb + 4];
            }
            #pragma unroll
            for (int mi = 0; mi < 4; mi++) {
                const int r0 = wm * 64 + mi * 16 + g;
                const int r1 = r0 + 8;
                uint32_t ah[4], al[4];
                ah[0] = Ah[r0 * SW + wb];
                ah[1] = Ah[r1 * SW + wb];
                ah[2] = Ah[r0 * SW + wb + 4];
                ah[3] = Ah[r1 * SW + wb + 4];
                al[0] = Al[r0 * SW + wb];
                al[1] = Al[r1 * SW + wb];
                al[2] = Al[r0 * SW + wb + 4];
                al[3] = Al[r1 * SW + wb + 4];
                #pragma unroll
                for (int ni = 0; ni < 4; ni++) {
                    mma16816(acc[mi][ni], ah, bh[ni]);
                    mma16816(acc[mi][ni], al, bh[ni]);
                    mma16816(acc[mi][ni], ah, bl[ni]);
                }
            }
        }
        __syncthreads();
    }

    float* pp = part + (size_t)p * BB * EE;
    #pragma unroll
    for (int mi = 0; mi < 4; mi++) {
        const int m0 = wm * 64 + mi * 16 + g;
        #pragma unroll
        for (int ni = 0; ni < 4; ni++) {
            const int col = fbase + wn * 32 + ni * 8 + tg * 2;
            *(float2*)(pp + (size_t)m0 * EE + col)       = make_float2(acc[mi][ni][0], acc[mi][ni][1]);
            *(float2*)(pp + (size_t)(m0 + 8) * EE + col) = make_float2(acc[mi][ni][2], acc[mi][ni][3]);
        }
    }
}

// out = (sum_p part[p] + bias) * scale
__global__ void __launch_bounds__(256) reduce_part(const float* __restrict__ bias,
                                                   float* __restrict__ out, float scale) {
    const int t = blockIdx.x * 256 + threadIdx.x;
    const int base = t * 4;
    const int col = base & (EE - 1);
    float4 a = *(const float4*)(g_part + base);
    float4 b = *(const float4*)(g_part + 1 * BB * EE + base);
    float4 c = *(const float4*)(g_part + 2 * BB * EE + base);
    float4 d = *(const float4*)(g_part + 3 * BB * EE + base);
    float4 bi = *(const float4*)(bias + col);
    float4 o;
    o.x = (a.x + b.x + c.x + d.x + bi.x) * scale;
    o.y = (a.y + b.y + c.y + d.y + bi.y) * scale;
    o.z = (a.z + b.z + c.z + d.z + bi.z) * scale;
    o.w = (a.w + b.w + c.w + d.w + bi.w) * scale;
    *(float4*)(out + base) = o;
}

// ---------------------------------------------------------------------------
// Kernel B: attention. One CTA (512 threads) per batch b.
// pass1: warp handles 4 consecutive s rows -> q smem traffic /4
// pass2: 4 s-groups of 128 threads, thread owns 4 d's x all 8 heads
// ---------------------------------------------------------------------------
__global__ void __launch_bounds__(512, 1) attn_kernel(const float* __restrict__ key,
                                                      const float* __restrict__ value,
                                                      const int* __restrict__ mask) {
    float* smem = (float*)dyn_smem;
    float* q_s = smem;            // 4096 floats
    float* sc  = smem + EE;       // 2048*8 = 16384 floats

    const int b = blockIdx.x;
    const int tid = threadIdx.x;
    const int warp = tid >> 5;
    const int lane = tid & 31;

    ((float4*)q_s)[tid]       = ((const float4*)(g_q + (size_t)b * EE))[tid];
    ((float4*)q_s)[tid + 512] = ((const float4*)(g_q + (size_t)b * EE))[tid + 512];
    __syncthreads();

    // ---- pass 1: scores; each warp does 4 consecutive s rows per iter ----
    const float* Kb = key + (size_t)b * SS * DD;
    const int*   Mb = mask + (size_t)b * SS;

    for (int s4 = warp * 4; s4 < SS; s4 += 64) {
        float4 kr[4][4];
        #pragma unroll
        for (int r = 0; r < 4; r++) {
            const float4* Kr = (const float4*)(Kb + (size_t)(s4 + r) * DD);
            kr[r][0] = Kr[lane];
            kr[r][1] = Kr[lane + 32];
            kr[r][2] = Kr[lane + 64];
            kr[r][3] = Kr[lane + 96];
        }
        float acc[HH][4];
        #pragma unroll
        for (int h = 0; h < HH; h++) {
            const float4* qh = (const float4*)(q_s + h * DD);
            float4 a0 = qh[lane], a1 = qh[lane + 32], a2 = qh[lane + 64], a3 = qh[lane + 96];
            #pragma unroll
            for (int r = 0; r < 4; r++)
                acc[h][r] = dot4(a0, kr[r][0]) + dot4(a1, kr[r][1])
                          + dot4(a2, kr[r][2]) + dot4(a3, kr[r][3]);
        }
        #pragma unroll
        for (int off = 16; off; off >>= 1) {
            #pragma unroll
            for (int h = 0; h < HH; h++) {
                #pragma unroll
                for (int r = 0; r < 4; r++)
                    acc[h][r] += __shfl_xor_sync(0xffffffffu, acc[h][r], off);
            }
        }
        #pragma unroll
        for (int r = 0; r < 4; r++) {
            const int mv = Mb[s4 + r];
            #pragma unroll
            for (int h = 0; h < HH; h++)
                if (lane == h) sc[(s4 + r) * 8 + h] = mv ? acc[h][r] : -1e9f;
        }
    }
    __syncthreads();

    // ---- softmax: warp h handles head h ----
    if (warp < HH) {
        float m = -3.0e38f;
        for (int i = lane; i < SS; i += 32) m = fmaxf(m, sc[i * 8 + warp]);
        #pragma unroll
        for (int off = 16; off; off >>= 1)
            m = fmaxf(m, __shfl_xor_sync(0xffffffffu, m, off));
        float sum = 0.0f;
        for (int i = lane; i < SS; i += 32) {
            float ev = __expf(sc[i * 8 + warp] - m);
            sc[i * 8 + warp] = ev;
            sum += ev;
        }
        #pragma unroll
        for (int off = 16; off; off >>= 1)
            sum += __shfl_xor_sync(0xffffffffu, sum, off);
        const float inv = 1.0f / sum;
        for (int i = lane; i < SS; i += 32) sc[i * 8 + warp] *= inv;
    }
    __syncthreads();

    // ---- pass 2: x = p @ V. 4 s-groups x 128 threads; thread: 4 d's, 8 heads.
    const int d4 = (tid & 127) * 4;
    const int sg = tid >> 7;             // 0..3
    const float* Vb = value + (size_t)b * SS * DD;

    float4 a0 = {0,0,0,0}, a1 = a0, a2 = a0, a3 = a0, a4 = a0, a5 = a0, a6 = a0, a7 = a0;
    const int s_beg = sg * 512;
    #pragma unroll 2
    for (int s = s_beg; s < s_beg + 512; s += 2) {
        float4 v0 = *(const float4*)(Vb + (size_t)s * DD + d4);
        float4 v1 = *(const float4*)(Vb + (size_t)(s + 1) * DD + d4);
        float4 p0 = *(const float4*)(sc + s * 8);
        float4 p1 = *(const float4*)(sc + s * 8 + 4);
        float4 p2 = *(const float4*)(sc + (s + 1) * 8);
        float4 p3 = *(const float4*)(sc + (s + 1) * 8 + 4);
        fma4(a0, p0.x, v0); fma4(a1, p0.y, v0); fma4(a2, p0.z, v0); fma4(a3, p0.w, v0);
        fma4(a4, p1.x, v0); fma4(a5, p1.y, v0); fma4(a6, p1.z, v0); fma4(a7, p1.w, v0);
        fma4(a0, p2.x, v1); fma4(a1, p2.y, v1); fma4(a2, p2.z, v1); fma4(a3, p2.w, v1);
        fma4(a4, p3.x, v1); fma4(a5, p3.y, v1); fma4(a6, p3.z, v1); fma4(a7, p3.w, v1);
    }
    __syncthreads();  // everyone done reading sc

    // combine 4 s-groups through smem: groups 0,1 write; 2,3 add; final sum of 2
    if (sg < 2) {
        float* dst = sc + sg * 4096;
        *(float4*)(dst + 0 * DD + d4) = a0;
        *(float4*)(dst + 1 * DD + d4) = a1;
        *(float4*)(dst + 2 * DD + d4) = a2;
        *(float4*)(dst + 3 * DD + d4) = a3;
        *(float4*)(dst + 4 * DD + d4) = a4;
        *(float4*)(dst + 5 * DD + d4) = a5;
        *(float4*)(dst + 6 * DD + d4) = a6;
        *(float4*)(dst + 7 * DD + d4) = a7;
    }
    __syncthreads();
    if (sg >= 2) {
        float* dst = sc + (sg - 2) * 4096;
        float4* p;
        p = (float4*)(dst + 0 * DD + d4); p->x += a0.x; p->y += a0.y; p->z += a0.z; p->w += a0.w;
        p = (float4*)(dst + 1 * DD + d4); p->x += a1.x; p->y += a1.y; p->z += a1.z; p->w += a1.w;
        p = (float4*)(dst + 2 * DD + d4); p->x += a2.x; p->y += a2.y; p->z += a2.z; p->w += a2.w;
        p = (float4*)(dst + 3 * DD + d4); p->x += a3.x; p->y += a3.y; p->z += a3.z; p->w += a3.w;
        p = (float4*)(dst + 4 * DD + d4); p->x += a4.x; p->y += a4.y; p->z += a4.z; p->w += a4.w;
        p = (float4*)(dst + 5 * DD + d4); p->x += a5.x; p->y += a5.y; p->z += a5.z; p->w += a5.w;
        p = (float4*)(dst + 6 * DD + d4); p->x += a6.x; p->y += a6.y; p->z += a6.z; p->w += a6.w;
        p = (float4*)(dst + 7 * DD + d4); p->x += a7.x; p->y += a7.y; p->z += a7.z; p->w += a7.w;
    }
    __syncthreads();

    // final combine across the 2 buffers; 512 threads x 8 floats
    const int idx = tid * 8;
    float4 u0 = *(float4*)(sc + idx);
    float4 u1 = *(float4*)(sc + idx + 4);
    float4 w0 = *(float4*)(sc + 4096 + idx);
    float4 w1 = *(float4*)(sc + 4096 + idx + 4);
    float4 r0, r1;
    r0.x = u0.x + w0.x; r0.y = u0.y + w0.y; r0.z = u0.z + w0.z; r0.w = u0.w + w0.w;
    r1.x = u1.x + w1.x; r1.y = u1.y + w1.y; r1.z = u1.z + w1.z; r1.w = u1.w + w1.w;
    *(float4*)(g_x + (size_t)b * EE + idx)     = r0;
    *(float4*)(g_x + (size_t)b * EE + idx + 4) = r1;
}

// ---------------------------------------------------------------------------
extern "C" void kernel_launch(void* const* d_in, const int* in_sizes, int n_in,
                              void* d_out, int out_size) {
    const float* query = (const float*)d_in[0];
    const float* key   = (const float*)d_in[1];
    const float* value = (const float*)d_in[2];
    const int*   mask  = (const int*)d_in[3];
    const float* W_in  = (const float*)d_in[4];
    const float* b_in  = (const float*)d_in[5];
    const float* W_out = (const float*)d_in[6];
    const float* b_out = (const float*)d_in[7];
    float* out = (float*)d_out;

    const int smem_attn = (EE + SS * 8) * sizeof(float);  // 81920 bytes
    cudaFuncSetAttribute(attn_kernel, cudaFuncAttributeMaxDynamicSharedMemorySize, smem_attn);
    cudaFuncSetAttribute(gemm_part<512, 128>,   cudaFuncAttributeMaxDynamicSharedMemorySize, GEMM_SMEM);
    cudaFuncSetAttribute(gemm_part<4096, 1024>, cudaFuncAttributeMaxDynamicSharedMemorySize, GEMM_SMEM);

    float* gq; cudaGetSymbolAddress((void**)&gq, g_q);
    float* gx; cudaGetSymbolAddress((void**)&gx, g_x);
    float* gp; cudaGetSymbolAddress((void**)&gp, g_part);

    dim3 ggrid(EE / 128, KSPLIT);

    gemm_part<512, 128><<<ggrid, 256, GEMM_SMEM>>>(query, W_in, gp);
    reduce_part<<<BB * EE / 1024, 256>>>(b_in, gq, 0.04419417382415922f);
    attn_kernel<<<BB, 512, smem_attn>>>(key, value, mask);
    gemm_part<4096, 1024><<<ggrid, 256, GEMM_SMEM>>>(gx, W_out, gp);
    reduce_part<<<BB * EE / 1024, 256>>>(b_out, out, 1.0f);
}

// round 6
// speedup vs baseline: 2.3333x; 1.3819x over previous
#include <cuda_runtime.h>
#include <cuda_bf16.h>
#include <cstdint>

#define HH 8
#define DD 512
#define BB 128
#define SS 2048
#define EE 4096   // HH*DD
#define KSPLIT 4

// Scratch (no allocations allowed)
__device__ float g_q[BB * EE];            // projected, pre-scaled query
__device__ float g_x[BB * EE];            // attention output
__device__ float g_part[KSPLIT * BB * EE];// k-split GEMM partials

// Single dynamic-smem symbol for the whole TU
extern __shared__ char dyn_smem[];

__device__ __forceinline__ float dot4(float4 a, float4 b) {
    return a.x * b.x + a.y * b.y + a.z * b.z + a.w * b.w;
}
__device__ __forceinline__ void fma4(float4& a, float p, float4 v) {
    a.x += p * v.x; a.y += p * v.y; a.z += p * v.z; a.w += p * v.w;
}

// m16n8k16 row.col bf16 mma, fp32 accumulate (standard PTX, sm_80+)
__device__ __forceinline__ void mma16816(float* c, const uint32_t* a, const uint32_t* b) {
    asm volatile(
        "mma.sync.aligned.m16n8k16.row.col.f32.bf16.bf16.f32 "
        "{%0,%1,%2,%3}, {%4,%5,%6,%7}, {%8,%9}, {%0,%1,%2,%3};"
        : "+f"(c[0]), "+f"(c[1]), "+f"(c[2]), "+f"(c[3])
        : "r"(a[0]), "r"(a[1]), "r"(a[2]), "r"(a[3]), "r"(b[0]), "r"(b[1]));
}

// pack float2 -> bf16x2 (hi) and residual (lo)
__device__ __forceinline__ uint32_t bfhi(float2 v) {
    __nv_bfloat162 h = __floats2bfloat162_rn(v.x, v.y);
    return *(uint32_t*)&h;
}
__device__ __forceinline__ uint32_t bflo(float2 v, uint32_t hbits) {
    __nv_bfloat162 h = *(__nv_bfloat162*)&hbits;
    float2 f = __bfloat1622float2(h);
    __nv_bfloat162 l = __floats2bfloat162_rn(v.x - f.x, v.y - f.y);
    return *(uint32_t*)&l;
}

// ===========================================================================
// gemm_part<K, KCHUNK>: part[p] = X[128,K_range] @ W[4096,K_range]^T
// BM=128, BN=64 -> grid (64, KSPLIT) = 256 CTAs, 2 CTAs/SM.
// ===========================================================================
#define KSTEP 32
#define SW 20                     // words per row in smem
#define ARR_A (128 * SW)          // 2560 words
#define ARR_B (64 * SW)           // 1280 words
#define BUFW (2 * ARR_A + 2 * ARR_B)  // 7680 words per buffer
#define GEMM_SMEM (2 * BUFW * 4)  // 61440 bytes

template <int K, int KCHUNK>
__global__ void __launch_bounds__(256, 2)
gemm_part(const float* __restrict__ X, const float* __restrict__ W,
          float* __restrict__ part) {
    uint32_t* sw = (uint32_t*)dyn_smem;
    const int tid = threadIdx.x;
    const int wid = tid >> 5;
    const int lane = tid & 31;
    const int g = lane >> 2;          // 0..7
    const int tg = lane & 3;          // 0..3
    const int wm = wid >> 2;          // 0..1: M half (64 rows)
    const int wn = wid & 3;           // 0..3: N quarter (16 cols)
    const int fbase = blockIdx.x * 64;
    const int p = blockIdx.y;
    const int kbeg = p * KCHUNK;

    float acc[4][2][4];
    #pragma unroll
    for (int mi = 0; mi < 4; mi++)
        #pragma unroll
        for (int ni = 0; ni < 2; ni++)
            #pragma unroll
            for (int r = 0; r < 4; r++) acc[mi][ni][r] = 0.0f;

    const int NC = KCHUNK / KSTEP;

    for (int c = 0; c < NC; c++) {
        const int q = c & 1;
        uint32_t* Ah = sw + q * BUFW;
        uint32_t* Al = Ah + ARR_A;
        uint32_t* Bh = Al + ARR_A;
        uint32_t* Bl = Bh + ARR_B;
        const int k0 = kbeg + c * KSTEP;

        #pragma unroll
        for (int i = 0; i < 4; i++) {
            const int idx = tid + i * 256;
            const int row = idx >> 3, q4 = idx & 7;
            float4 v = *(const float4*)(X + (size_t)row * K + k0 + q4 * 4);
            uint32_t h01 = bfhi(make_float2(v.x, v.y));
            uint32_t h23 = bfhi(make_float2(v.z, v.w));
            uint32_t l01 = bflo(make_float2(v.x, v.y), h01);
            uint32_t l23 = bflo(make_float2(v.z, v.w), h23);
            const int off = row * SW + q4 * 2;
            *(uint2*)(Ah + off) = make_uint2(h01, h23);
            *(uint2*)(Al + off) = make_uint2(l01, l23);
        }
        #pragma unroll
        for (int i = 0; i < 2; i++) {
            const int idx = tid + i * 256;
            const int row = idx >> 3, q4 = idx & 7;
            float4 v = *(const float4*)(W + (size_t)(fbase + row) * K + k0 + q4 * 4);
            uint32_t h01 = bfhi(make_float2(v.x, v.y));
            uint32_t h23 = bfhi(make_float2(v.z, v.w));
            uint32_t l01 = bflo(make_float2(v.x, v.y), h01);
            uint32_t l23 = bflo(make_float2(v.z, v.w), h23);
            const int off = row * SW + q4 * 2;
            *(uint2*)(Bh + off) = make_uint2(h01, h23);
            *(uint2*)(Bl + off) = make_uint2(l01, l23);
        }
        __syncthreads();

        #pragma unroll
        for (int sub = 0; sub < 2; sub++) {
            const int wb = sub * 8 + tg;
            uint32_t bh[2][2], bl[2][2];
            #pragma unroll
            for (int ni = 0; ni < 2; ni++) {
                const int r = wn * 16 + ni * 8 + g;
                bh[ni][0] = Bh[r * SW + wb];
                bh[ni][1] = Bh[r * SW + wb + 4];
                bl[ni][0] = Bl[r * SW + wb];
                bl[ni][1] = Bl[r * SW + wb + 4];
            }
            #pragma unroll
            for (int mi = 0; mi < 4; mi++) {
                const int r0 = wm * 64 + mi * 16 + g;
                const int r1 = r0 + 8;
                uint32_t ah[4], al[4];
                ah[0] = Ah[r0 * SW + wb];
                ah[1] = Ah[r1 * SW + wb];
                ah[2] = Ah[r0 * SW + wb + 4];
                ah[3] = Ah[r1 * SW + wb + 4];
                al[0] = Al[r0 * SW + wb];
                al[1] = Al[r1 * SW + wb];
                al[2] = Al[r0 * SW + wb + 4];
                al[3] = Al[r1 * SW + wb + 4];
                #pragma unroll
                for (int ni = 0; ni < 2; ni++) {
                    mma16816(acc[mi][ni], ah, bh[ni]);
                    mma16816(acc[mi][ni], al, bh[ni]);
                    mma16816(acc[mi][ni], ah, bl[ni]);
                }
            }
        }
        __syncthreads();
    }

    float* pp = part + (size_t)p * BB * EE;
    #pragma unroll
    for (int mi = 0; mi < 4; mi++) {
        const int m0 = wm * 64 + mi * 16 + g;
        #pragma unroll
        for (int ni = 0; ni < 2; ni++) {
            const int col = fbase + wn * 16 + ni * 8 + tg * 2;
            *(float2*)(pp + (size_t)m0 * EE + col)       = make_float2(acc[mi][ni][0], acc[mi][ni][1]);
            *(float2*)(pp + (size_t)(m0 + 8) * EE + col) = make_float2(acc[mi][ni][2], acc[mi][ni][3]);
        }
    }
}

// out = (sum_p part[p] + bias) * scale
__global__ void __launch_bounds__(256) reduce_part(const float* __restrict__ bias,
                                                   float* __restrict__ out, float scale) {
    const int t = blockIdx.x * 256 + threadIdx.x;
    const int base = t * 4;
    const int col = base & (EE - 1);
    float4 a = *(const float4*)(g_part + base);
    float4 b = *(const float4*)(g_part + 1 * BB * EE + base);
    float4 c = *(const float4*)(g_part + 2 * BB * EE + base);
    float4 d = *(const float4*)(g_part + 3 * BB * EE + base);
    float4 bi = *(const float4*)(bias + col);
    float4 o;
    o.x = (a.x + b.x + c.x + d.x + bi.x) * scale;
    o.y = (a.y + b.y + c.y + d.y + bi.y) * scale;
    o.z = (a.z + b.z + c.z + d.z + bi.z) * scale;
    o.w = (a.w + b.w + c.w + d.w + bi.w) * scale;
    *(float4*)(out + base) = o;
}

// ---------------------------------------------------------------------------
// Kernel B: attention. One CTA (512 threads) per batch b.
// pass1: mma.sync. scores[2048,8] = K @ q^T, bf16 hi/lo 3-term split.
//   A-frags: K loaded direct from global (float2 pairs), converted in regs.
//   B-frags: q pre-packed into frag-layout smem table qbA/qbB.
// pass2: FFMA, 4 s-groups x 128 threads (unchanged).
// smem: sc fp32 [2048][8] @0 (64KB), qbA @64K (8KB), qbB @72K (8KB)
// ---------------------------------------------------------------------------
__global__ void __launch_bounds__(512, 1) attn_kernel(const float* __restrict__ key,
                                                      const float* __restrict__ value,
                                                      const int* __restrict__ mask) {
    float* sc = (float*)dyn_smem;                       // 16384 floats
    uint2* qbA = (uint2*)(dyn_smem + 65536);            // [32 ks][32 lane]
    uint2* qbB = (uint2*)(dyn_smem + 65536 + 8192);

    const int b = blockIdx.x;
    const int tid = threadIdx.x;
    const int warp = tid >> 5;
    const int lane = tid & 31;
    const int gid = lane >> 2;
    const int tg = lane & 3;

    // build q B-frag tables (hi/lo). entry (ks, L): h=L>>2, d0=ks*16+(L&3)*2
    for (int idx = tid; idx < 1024; idx += 512) {
        const int ks = idx >> 5, L = idx & 31;
        const int h = L >> 2, d0 = ks * 16 + (L & 3) * 2;
        const float* qp = g_q + (size_t)b * EE + h * DD + d0;
        float2 v0 = make_float2(qp[0], qp[1]);
        float2 v1 = make_float2(qp[8], qp[9]);
        uint32_t h0 = bfhi(v0), l0 = bflo(v0, h0);
        uint32_t h1 = bfhi(v1), l1 = bflo(v1, h1);
        qbA[idx] = make_uint2(h0, h1);
        qbB[idx] = make_uint2(l0, l1);
    }
    __syncthreads();

    // ---- pass 1: scores via mma. warp handles 8 m-tiles of 16 s. ----
    const float* Kb = key + (size_t)b * SS * DD;
    const int*   Mb = mask + (size_t)b * SS;

    for (int i = 0; i < 8; i++) {
        const int mt = warp * 8 + i;
        const int s0 = mt * 16 + gid;
        const float* K0 = Kb + (size_t)s0 * DD + tg * 2;
        float c[4] = {0.0f, 0.0f, 0.0f, 0.0f};
        #pragma unroll 4
        for (int ks = 0; ks < 32; ks++) {
            const float* kp = K0 + ks * 16;
            float2 va0 = *(const float2*)(kp);
            float2 va1 = *(const float2*)(kp + 8 * DD);
            float2 va2 = *(const float2*)(kp + 8);
            float2 va3 = *(const float2*)(kp + 8 * DD + 8);
            uint32_t ah[4], al[4];
            ah[0] = bfhi(va0); al[0] = bflo(va0, ah[0]);
            ah[1] = bfhi(va1); al[1] = bflo(va1, ah[1]);
            ah[2] = bfhi(va2); al[2] = bflo(va2, ah[2]);
            ah[3] = bfhi(va3); al[3] = bflo(va3, ah[3]);
            uint2 bh = qbA[ks * 32 + lane];
            uint2 bl = qbB[ks * 32 + lane];
            mma16816(c, ah, (const uint32_t*)&bh);
            mma16816(c, al, (const uint32_t*)&bh);
            mma16816(c, ah, (const uint32_t*)&bl);
        }
        const int s1 = s0 + 8, h0 = tg * 2;
        const int m0 = Mb[s0], m1 = Mb[s1];
        sc[s0 * 8 + h0]     = m0 ? c[0] : -1e9f;
        sc[s0 * 8 + h0 + 1] = m0 ? c[1] : -1e9f;
        sc[s1 * 8 + h0]     = m1 ? c[2] : -1e9f;
        sc[s1 * 8 + h0 + 1] = m1 ? c[3] : -1e9f;
    }
    __syncthreads();

    // ---- softmax: warp h handles head h ----
    if (warp < HH) {
        float m = -3.0e38f;
        for (int i = lane; i < SS; i += 32) m = fmaxf(m, sc[i * 8 + warp]);
        #pragma unroll
        for (int off = 16; off; off >>= 1)
            m = fmaxf(m, __shfl_xor_sync(0xffffffffu, m, off));
        float sum = 0.0f;
        for (int i = lane; i < SS; i += 32) {
            float ev = __expf(sc[i * 8 + warp] - m);
            sc[i * 8 + warp] = ev;
            sum += ev;
        }
        #pragma unroll
        for (int off = 16; off; off >>= 1)
            sum += __shfl_xor_sync(0xffffffffu, sum, off);
        const float inv = 1.0f / sum;
        for (int i = lane; i < SS; i += 32) sc[i * 8 + warp] *= inv;
    }
    __syncthreads();

    // ---- pass 2: x = p @ V. 4 s-groups x 128 threads; thread: 4 d's, 8 heads.
    const int d4 = (tid & 127) * 4;
    const int sg = tid >> 7;             // 0..3
    const float* Vb = value + (size_t)b * SS * DD;

    float4 a0 = {0,0,0,0}, a1 = a0, a2 = a0, a3 = a0, a4 = a0, a5 = a0, a6 = a0, a7 = a0;
    const int s_beg = sg * 512;
    #pragma unroll 2
    for (int s = s_beg; s < s_beg + 512; s += 2) {
        float4 v0 = *(const float4*)(Vb + (size_t)s * DD + d4);
        float4 v1 = *(const float4*)(Vb + (size_t)(s + 1) * DD + d4);
        float4 p0 = *(const float4*)(sc + s * 8);
        float4 p1 = *(const float4*)(sc + s * 8 + 4);
        float4 p2 = *(const float4*)(sc + (s + 1) * 8);
        float4 p3 = *(const float4*)(sc + (s + 1) * 8 + 4);
        fma4(a0, p0.x, v0); fma4(a1, p0.y, v0); fma4(a2, p0.z, v0); fma4(a3, p0.w, v0);
        fma4(a4, p1.x, v0); fma4(a5, p1.y, v0); fma4(a6, p1.z, v0); fma4(a7, p1.w, v0);
        fma4(a0, p2.x, v1); fma4(a1, p2.y, v1); fma4(a2, p2.z, v1); fma4(a3, p2.w, v1);
        fma4(a4, p3.x, v1); fma4(a5, p3.y, v1); fma4(a6, p3.z, v1); fma4(a7, p3.w, v1);
    }
    __syncthreads();  // everyone done reading sc

    // combine 4 s-groups through smem (sc reused): 0,1 write; 2,3 add; sum 2
    if (sg < 2) {
        float* dst = sc + sg * 4096;
        *(float4*)(dst + 0 * DD + d4) = a0;
        *(float4*)(dst + 1 * DD + d4) = a1;
        *(float4*)(dst + 2 * DD + d4) = a2;
        *(float4*)(dst + 3 * DD + d4) = a3;
        *(float4*)(dst + 4 * DD + d4) = a4;
        *(float4*)(dst + 5 * DD + d4) = a5;
        *(float4*)(dst + 6 * DD + d4) = a6;
        *(float4*)(dst + 7 * DD + d4) = a7;
    }
    __syncthreads();
    if (sg >= 2) {
        float* dst = sc + (sg - 2) * 4096;
        float4* p;
        p = (float4*)(dst + 0 * DD + d4); p->x += a0.x; p->y += a0.y; p->z += a0.z; p->w += a0.w;
        p = (float4*)(dst + 1 * DD + d4); p->x += a1.x; p->y += a1.y; p->z += a1.z; p->w += a1.w;
        p = (float4*)(dst + 2 * DD + d4); p->x += a2.x; p->y += a2.y; p->z += a2.z; p->w += a2.w;
        p = (float4*)(dst + 3 * DD + d4); p->x += a3.x; p->y += a3.y; p->z += a3.z; p->w += a3.w;
        p = (float4*)(dst + 4 * DD + d4); p->x += a4.x; p->y += a4.y; p->z += a4.z; p->w += a4.w;
        p = (float4*)(dst + 5 * DD + d4); p->x += a5.x; p->y += a5.y; p->z += a5.z; p->w += a5.w;
        p = (float4*)(dst + 6 * DD + d4); p->x += a6.x; p->y += a6.y; p->z += a6.z; p->w += a6.w;
        p = (float4*)(dst + 7 * DD + d4); p->x += a7.x; p->y += a7.y; p->z += a7.z; p->w += a7.w;
    }
    __syncthreads();

    const int idx = tid * 8;
    float4 u0 = *(float4*)(sc + idx);
    float4 u1 = *(float4*)(sc + idx + 4);
    float4 w0 = *(float4*)(sc + 4096 + idx);
    float4 w1 = *(float4*)(sc + 4096 + idx + 4);
    float4 r0, r1;
    r0.x = u0.x + w0.x; r0.y = u0.y + w0.y; r0.z = u0.z + w0.z; r0.w = u0.w + w0.w;
    r1.x = u1.x + w1.x; r1.y = u1.y + w1.y; r1.z = u1.z + w1.z; r1.w = u1.w + w1.w;
    *(float4*)(g_x + (size_t)b * EE + idx)     = r0;
    *(float4*)(g_x + (size_t)b * EE + idx + 4) = r1;
}

// ---------------------------------------------------------------------------
extern "C" void kernel_launch(void* const* d_in, const int* in_sizes, int n_in,
                              void* d_out, int out_size) {
    const float* query = (const float*)d_in[0];
    const float* key   = (const float*)d_in[1];
    const float* value = (const float*)d_in[2];
    const int*   mask  = (const int*)d_in[3];
    const float* W_in  = (const float*)d_in[4];
    const float* b_in  = (const float*)d_in[5];
    const float* W_out = (const float*)d_in[6];
    const float* b_out = (const float*)d_in[7];
    float* out = (float*)d_out;

    const int smem_attn = 81920;  // sc 64K + qbA 8K + qbB 8K
    cudaFuncSetAttribute(attn_kernel, cudaFuncAttributeMaxDynamicSharedMemorySize, smem_attn);
    cudaFuncSetAttribute(gemm_part<512, 128>,   cudaFuncAttributeMaxDynamicSharedMemorySize, GEMM_SMEM);
    cudaFuncSetAttribute(gemm_part<4096, 1024>, cudaFuncAttributeMaxDynamicSharedMemorySize, GEMM_SMEM);

    float* gq; cudaGetSymbolAddress((void**)&gq, g_q);
    float* gx; cudaGetSymbolAddress((void**)&gx, g_x);
    float* gp; cudaGetSymbolAddress((void**)&gp, g_part);

    dim3 ggrid(EE / 64, KSPLIT);   // 256 CTAs

    gemm_part<512, 128><<<ggrid, 256, GEMM_SMEM>>>(query, W_in, gp);
    reduce_part<<<BB * EE / 1024, 256>>>(b_in, gq, 0.04419417382415922f);
    attn_kernel<<<BB, 512, smem_attn>>>(key, value, mask);
    gemm_part<4096, 1024><<<ggrid, 256, GEMM_SMEM>>>(gx, W_out, gp);
    reduce_part<<<BB * EE / 1024, 256>>>(b_out, out, 1.0f);
}